// round 9
// baseline (speedup 1.0000x reference)
#include <cuda_runtime.h>
#include <cuda_bf16.h>
#include <cstdint>

#define HIDDEN 128
#define MAX_NODES 50048
#define MAX_EDGES 800000

// ---------------- scratch (static device globals; no allocation) -------------
__device__ float    g_agg[(size_t)MAX_NODES * HIDDEN];
__device__ float    g_colsum[HIDDEN];
__device__ float    g_b1eff[HIDDEN];
__device__ uint32_t g_W1t[8 * 4096];   // W1 tf32, transposed+permuted, 8 k-tiles
__device__ uint32_t g_W2t[4 * 4096];   // W2 tf32, same, 4 k-tiles

// ---------------- kernel 1: zero agg + colsum -------------------------------
__global__ void zero_kernel(int n_nodes) {
    size_t total = (size_t)n_nodes * HIDDEN;
    size_t i = (size_t)blockIdx.x * blockDim.x + threadIdx.x;
    size_t stride = (size_t)gridDim.x * blockDim.x;
    for (size_t idx = i; idx < total; idx += stride) g_agg[idx] = 0.0f;
    if (i < HIDDEN) g_colsum[i] = 0.0f;
}

// ---------------- kernel 2: scatter-add + edge_attr copy + colsum ------------
// x4 edge unroll; single-wave launch (148 SMs x 6 blocks @ 40 regs).
template<typename IDX>
__global__ void __launch_bounds__(256, 6)
scatter_copy_kernel(const float4* __restrict__ ea,
                    const IDX* __restrict__ recv,
                    float4* __restrict__ out_ea,
                    int n_edges) {
    int wl   = threadIdx.x >> 5;
    int lane = threadIdx.x & 31;
    int gw   = blockIdx.x * 8 + wl;
    int nW   = gridDim.x * 8;

    float4 acc = make_float4(0.f, 0.f, 0.f, 0.f);

    int e4_limit = n_edges & ~3;
    for (int e = gw * 4; e + 3 < e4_limit; e += nW * 4) {
        int r0 = (int)__ldcs(&recv[e + 0]);
        int r1 = (int)__ldcs(&recv[e + 1]);
        int r2 = (int)__ldcs(&recv[e + 2]);
        int r3 = (int)__ldcs(&recv[e + 3]);
        float4 v0 = __ldcs(&ea[(size_t)(e + 0) * 32 + lane]);
        float4 v1 = __ldcs(&ea[(size_t)(e + 1) * 32 + lane]);
        float4 v2 = __ldcs(&ea[(size_t)(e + 2) * 32 + lane]);
        float4 v3 = __ldcs(&ea[(size_t)(e + 3) * 32 + lane]);
        if (out_ea) {
            __stcs(&out_ea[(size_t)(e + 0) * 32 + lane], v0);
            __stcs(&out_ea[(size_t)(e + 1) * 32 + lane], v1);
            __stcs(&out_ea[(size_t)(e + 2) * 32 + lane], v2);
            __stcs(&out_ea[(size_t)(e + 3) * 32 + lane], v3);
        }
        acc.x += v0.x + v1.x + v2.x + v3.x;
        acc.y += v0.y + v1.y + v2.y + v3.y;
        acc.z += v0.z + v1.z + v2.z + v3.z;
        acc.w += v0.w + v1.w + v2.w + v3.w;
        float* d0 = g_agg + (size_t)r0 * HIDDEN + lane * 4;
        float* d1 = g_agg + (size_t)r1 * HIDDEN + lane * 4;
        float* d2 = g_agg + (size_t)r2 * HIDDEN + lane * 4;
        float* d3 = g_agg + (size_t)r3 * HIDDEN + lane * 4;
        asm volatile("red.global.add.v4.f32 [%0], {%1,%2,%3,%4};"
                     :: "l"(d0), "f"(v0.x), "f"(v0.y), "f"(v0.z), "f"(v0.w) : "memory");
        asm volatile("red.global.add.v4.f32 [%0], {%1,%2,%3,%4};"
                     :: "l"(d1), "f"(v1.x), "f"(v1.y), "f"(v1.z), "f"(v1.w) : "memory");
        asm volatile("red.global.add.v4.f32 [%0], {%1,%2,%3,%4};"
                     :: "l"(d2), "f"(v2.x), "f"(v2.y), "f"(v2.z), "f"(v2.w) : "memory");
        asm volatile("red.global.add.v4.f32 [%0], {%1,%2,%3,%4};"
                     :: "l"(d3), "f"(v3.x), "f"(v3.y), "f"(v3.z), "f"(v3.w) : "memory");
    }
    for (int e = e4_limit + gw; e < n_edges; e += nW) {
        int r = (int)__ldcs(&recv[e]);
        float4 v = __ldcs(&ea[(size_t)e * 32 + lane]);
        if (out_ea) __stcs(&out_ea[(size_t)e * 32 + lane], v);
        acc.x += v.x; acc.y += v.y; acc.z += v.z; acc.w += v.w;
        float* dst = g_agg + (size_t)r * HIDDEN + lane * 4;
        asm volatile("red.global.add.v4.f32 [%0], {%1,%2,%3,%4};"
                     :: "l"(dst), "f"(v.x), "f"(v.y), "f"(v.z), "f"(v.w) : "memory");
    }

    __shared__ float4 reds[8][32];
    reds[wl][lane] = acc;
    __syncthreads();
    if (wl == 0) {
        float4 s = reds[0][lane];
        #pragma unroll
        for (int w = 1; w < 8; w++) {
            float4 t = reds[w][lane];
            s.x += t.x; s.y += t.y; s.z += t.z; s.w += t.w;
        }
        atomicAdd(&g_colsum[lane * 4 + 0], s.x);
        atomicAdd(&g_colsum[lane * 4 + 1], s.y);
        atomicAdd(&g_colsum[lane * 4 + 2], s.z);
        atomicAdd(&g_colsum[lane * 4 + 3], s.w);
    }
}

// ---------------- kernel 3: edge_index passthrough ---------------------------
__global__ void ei_copy_i32_as_float_kernel(const int* __restrict__ ei,
                                            float* __restrict__ out, int n) {
    int i = blockIdx.x * blockDim.x + threadIdx.x;
    if (i < n) __stcs(&out[i], (float)__ldcs(&ei[i]));
}
__global__ void ei_copy_raw64_kernel(const long long* __restrict__ ei,
                                     long long* __restrict__ out, int n) {
    int i = blockIdx.x * blockDim.x + threadIdx.x;
    if (i < n) __stcs(&out[i], __ldcs(&ei[i]));
}

// ---------------- kernel 4: fold mean into bias (parallel) -------------------
__global__ void b1eff_kernel(const float* __restrict__ W1,
                             const float* __restrict__ b1, int n_nodes) {
    int j = blockIdx.x;
    int k = threadIdx.x;
    float inv = 1.0f / (float)n_nodes;
    float v = g_colsum[k] * inv * __ldg(&W1[(size_t)(HIDDEN + k) * HIDDEN + j]);
    #pragma unroll
    for (int o = 16; o > 0; o >>= 1) v += __shfl_down_sync(0xffffffffu, v, o);
    __shared__ float red[4];
    if ((k & 31) == 0) red[k >> 5] = v;
    __syncthreads();
    if (k == 0)
        g_b1eff[j] = b1[j] - (red[0] + red[1] + red[2] + red[3]);
}

// ---------------- weight pre-convert -----------------------------------------
__device__ __forceinline__ uint32_t f2tf32(float f) {
    uint32_t u;
    asm("cvt.rna.tf32.f32 %0, %1;" : "=r"(u) : "f"(f));
    return u;
}

__global__ void wconv_kernel(const float* __restrict__ W,
                             uint32_t* __restrict__ out) {
    int t   = blockIdx.x;
    int tid = threadIdx.x;            // 256
    #pragma unroll
    for (int j = 0; j < 16; j++) {
        int o  = j * 256 + tid;
        int n  = o >> 5;
        int pk = o & 31;
        int k  = (pk & 7) * 4 + (pk >> 3);
        out[t * 4096 + o] = f2tf32(__ldg(&W[(size_t)(t * 32 + k) * HIDDEN + n]));
    }
}

// ---------------- fused 2-layer tf32 MLP -------------------------------------
#define SPAD 37
#define HS_W 4736
#define ARENA_WORDS 23936

__global__ void __launch_bounds__(256)
fused_mlp_kernel(const float* __restrict__ A0,
                 const float* __restrict__ A1,
                 const float* __restrict__ b2,
                 float* __restrict__ out, int n_rows) {
    extern __shared__ uint32_t sm[];
    uint32_t* Hs    = sm;
    uint32_t* As    = sm;
    uint32_t* Bs    = sm + HS_W;
    uint32_t* Bs2   = sm + 4 * HS_W;
    float*    sB1   = (float*)(sm + 23680);
    float*    sB2   = (float*)(sm + 23808);

    int tid  = threadIdx.x;
    int lane = tid & 31;
    int wid  = tid >> 5;
    int q    = lane & 3;
    int lg   = lane >> 2;
    int wm   = wid >> 2;
    int wn   = wid & 3;
    int Rw   = wm * 64;
    int Nw   = wn * 32;
    int row0 = blockIdx.x * 128;

    if (tid < HIDDEN) {
        sB1[tid] = g_b1eff[tid];
        sB2[tid] = b2[tid];
    }

    float c1[4][4][4];
    #pragma unroll
    for (int i = 0; i < 4; i++)
        #pragma unroll
        for (int j = 0; j < 4; j++)
            #pragma unroll
            for (int t = 0; t < 4; t++) c1[i][j][t] = 0.0f;

    float4 ar[4];
    uint4  br[4];

    {
        #pragma unroll
        for (int it = 0; it < 4; it++) {
            int idx = tid + it * 256;
            int row = idx >> 3, tt = idx & 7;
            int grow = row0 + row;
            ar[it] = (grow < n_rows)
                ? __ldg((const float4*)&A0[(size_t)grow * HIDDEN + tt * 4])
                : make_float4(0.f, 0.f, 0.f, 0.f);
        }
        const uint4* src = (const uint4*)g_W1t;
        #pragma unroll
        for (int j = 0; j < 4; j++) br[j] = __ldg(&src[j * 256 + tid]);
    }

    for (int t = 0; t < 8; t++) {
        #pragma unroll
        for (int it = 0; it < 4; it++) {
            int idx = tid + it * 256;
            int row = idx >> 3, tt = idx & 7;
            uint32_t* dst = &As[row * SPAD + tt];
            dst[0]  = f2tf32(ar[it].x);
            dst[8]  = f2tf32(ar[it].y);
            dst[16] = f2tf32(ar[it].z);
            dst[24] = f2tf32(ar[it].w);
        }
        #pragma unroll
        for (int j = 0; j < 4; j++) {
            int o  = (j * 256 + tid) * 4;
            int n  = o >> 5;
            int pk = o & 31;
            uint32_t* dst = &Bs[n * SPAD + pk];
            dst[0] = br[j].x; dst[1] = br[j].y;
            dst[2] = br[j].z; dst[3] = br[j].w;
        }
        __syncthreads();

        if (t < 7) {
            const float* Asrc = (t + 1 >= 4) ? A1 : A0;
            int kb = ((t + 1) & 3) * 32;
            #pragma unroll
            for (int it = 0; it < 4; it++) {
                int idx = tid + it * 256;
                int row = idx >> 3, tt = idx & 7;
                int grow = row0 + row;
                ar[it] = (grow < n_rows)
                    ? __ldg((const float4*)&Asrc[(size_t)grow * HIDDEN + kb + tt * 4])
                    : make_float4(0.f, 0.f, 0.f, 0.f);
            }
            const uint4* src = (const uint4*)&g_W1t[(t + 1) * 4096];
            #pragma unroll
            for (int j = 0; j < 4; j++) br[j] = __ldg(&src[j * 256 + tid]);
        }

        #pragma unroll
        for (int s = 0; s < 4; s++) {
            uint32_t a[4][4];
            #pragma unroll
            for (int mt = 0; mt < 4; mt++) {
                int r = Rw + mt * 16 + lg;
                int o0 = r * SPAD + q * 8 + 2 * s;
                int o1 = (r + 8) * SPAD + q * 8 + 2 * s;
                a[mt][0] = As[o0]; a[mt][2] = As[o0 + 1];
                a[mt][1] = As[o1]; a[mt][3] = As[o1 + 1];
            }
            uint32_t b[4][2];
            #pragma unroll
            for (int nt = 0; nt < 4; nt++) {
                int ob = (Nw + nt * 8 + lg) * SPAD + q * 8 + 2 * s;
                b[nt][0] = Bs[ob]; b[nt][1] = Bs[ob + 1];
            }
            #pragma unroll
            for (int mt = 0; mt < 4; mt++)
                #pragma unroll
                for (int nt = 0; nt < 4; nt++)
                    asm volatile(
                        "mma.sync.aligned.m16n8k8.row.col.f32.tf32.tf32.f32 "
                        "{%0,%1,%2,%3}, {%4,%5,%6,%7}, {%8,%9}, {%0,%1,%2,%3};"
                        : "+f"(c1[mt][nt][0]), "+f"(c1[mt][nt][1]),
                          "+f"(c1[mt][nt][2]), "+f"(c1[mt][nt][3])
                        : "r"(a[mt][0]), "r"(a[mt][1]),
                          "r"(a[mt][2]), "r"(a[mt][3]),
                          "r"(b[nt][0]), "r"(b[nt][1]));
        }
        __syncthreads();
    }

    // phase 2
    #pragma unroll
    for (int mt = 0; mt < 4; mt++) {
        int r0 = Rw + mt * 16 + lg;
        int r1 = r0 + 8;
        #pragma unroll
        for (int nt = 0; nt < 4; nt++) {
            int col = Nw + nt * 8 + 2 * q;
            int lk0 = nt * 8 + 2 * q;
            float bb0 = sB1[col], bb1 = sB1[col + 1];
            float v0 = fmaxf(c1[mt][nt][0] + bb0, 0.f);
            float v1 = fmaxf(c1[mt][nt][1] + bb1, 0.f);
            float v2 = fmaxf(c1[mt][nt][2] + bb0, 0.f);
            float v3 = fmaxf(c1[mt][nt][3] + bb1, 0.f);
            int p0 = (lk0 & 3) * 8 + (lk0 >> 2);
            int p1 = ((lk0 + 1) & 3) * 8 + ((lk0 + 1) >> 2);
            uint32_t* hb = &Hs[wn * HS_W];
            hb[r0 * SPAD + p0] = f2tf32(v0);
            hb[r0 * SPAD + p1] = f2tf32(v1);
            hb[r1 * SPAD + p0] = f2tf32(v2);
            hb[r1 * SPAD + p1] = f2tf32(v3);
        }
    }

    float c2[4][4][4];
    #pragma unroll
    for (int i = 0; i < 4; i++)
        #pragma unroll
        for (int j = 0; j < 4; j++)
            #pragma unroll
            for (int t = 0; t < 4; t++) c2[i][j][t] = 0.0f;

    {
        const uint4* src = (const uint4*)g_W2t;
        #pragma unroll
        for (int j = 0; j < 4; j++) br[j] = __ldg(&src[j * 256 + tid]);
    }

    for (int s = 0; s < 4; s++) {
        #pragma unroll
        for (int j = 0; j < 4; j++) {
            int o  = (j * 256 + tid) * 4;
            int n  = o >> 5;
            int pk = o & 31;
            uint32_t* dst = &Bs2[n * SPAD + pk];
            dst[0] = br[j].x; dst[1] = br[j].y;
            dst[2] = br[j].z; dst[3] = br[j].w;
        }
        __syncthreads();

        if (s < 3) {
            const uint4* src = (const uint4*)&g_W2t[(s + 1) * 4096];
            #pragma unroll
            for (int j = 0; j < 4; j++) br[j] = __ldg(&src[j * 256 + tid]);
        }

        const uint32_t* Hb = &Hs[s * HS_W];
        #pragma unroll
        for (int ss = 0; ss < 4; ss++) {
            uint32_t a[4][4];
            #pragma unroll
            for (int mt = 0; mt < 4; mt++) {
                int r = Rw + mt * 16 + lg;
                int o0 = r * SPAD + q * 8 + 2 * ss;
                int o1 = (r + 8) * SPAD + q * 8 + 2 * ss;
                a[mt][0] = Hb[o0]; a[mt][2] = Hb[o0 + 1];
                a[mt][1] = Hb[o1]; a[mt][3] = Hb[o1 + 1];
            }
            uint32_t b[4][2];
            #pragma unroll
            for (int nt = 0; nt < 4; nt++) {
                int ob = (Nw + nt * 8 + lg) * SPAD + q * 8 + 2 * ss;
                b[nt][0] = Bs2[ob]; b[nt][1] = Bs2[ob + 1];
            }
            #pragma unroll
            for (int mt = 0; mt < 4; mt++)
                #pragma unroll
                for (int nt = 0; nt < 4; nt++)
                    asm volatile(
                        "mma.sync.aligned.m16n8k8.row.col.f32.tf32.tf32.f32 "
                        "{%0,%1,%2,%3}, {%4,%5,%6,%7}, {%8,%9}, {%0,%1,%2,%3};"
                        : "+f"(c2[mt][nt][0]), "+f"(c2[mt][nt][1]),
                          "+f"(c2[mt][nt][2]), "+f"(c2[mt][nt][3])
                        : "r"(a[mt][0]), "r"(a[mt][1]),
                          "r"(a[mt][2]), "r"(a[mt][3]),
                          "r"(b[nt][0]), "r"(b[nt][1]));
        }
        __syncthreads();
    }

    #pragma unroll
    for (int mt = 0; mt < 4; mt++) {
        int r0g = row0 + Rw + mt * 16 + lg;
        int r1g = r0g + 8;
        #pragma unroll
        for (int nt = 0; nt < 4; nt++) {
            int col = Nw + nt * 8 + 2 * q;
            float bb0 = sB2[col], bb1 = sB2[col + 1];
            if (r0g < n_rows)
                *(float2*)&out[(size_t)r0g * HIDDEN + col] =
                    make_float2(c2[mt][nt][0] + bb0, c2[mt][nt][1] + bb1);
            if (r1g < n_rows)
                *(float2*)&out[(size_t)r1g * HIDDEN + col] =
                    make_float2(c2[mt][nt][2] + bb0, c2[mt][nt][3] + bb1);
        }
    }
}

// ---------------- launcher ---------------------------------------------------
extern "C" void kernel_launch(void* const* d_in, const int* in_sizes, int n_in,
                              void* d_out, int out_size) {
    const float* node_attr  = (const float*)d_in[0];
    const void*  edge_index = d_in[1];
    const float* edge_attr  = (const float*)d_in[2];
    const float* W1         = (const float*)d_in[3];
    const float* b1         = (const float*)d_in[4];
    const float* W2         = (const float*)d_in[5];
    const float* b2         = (const float*)d_in[6];

    int n_nodes = in_sizes[0] / HIDDEN;
    int n_edges = in_sizes[1] / 2;

    size_t x_el  = (size_t)n_nodes * HIDDEN;
    size_t ei_el = 2 * (size_t)n_edges;
    size_t ea_el = (size_t)n_edges * HIDDEN;

    float* out   = (float*)d_out;
    float* out_x = out;

    size_t os = (size_t)out_size;
    bool idx64 = false;
    float*     out_ei_f   = nullptr;
    long long* out_ei_raw = nullptr;
    float*     out_ea     = nullptr;
    if (os == x_el + ei_el + ea_el) {
        idx64 = false;
        out_ei_f = out + x_el;
        out_ea   = out + x_el + ei_el;
    } else if (os == x_el + 2 * ei_el + ea_el) {
        idx64 = true;
        out_ei_raw = (long long*)(out + x_el);
        out_ea     = out + x_el + 2 * ei_el;
    }

    float*    d_agg;  cudaGetSymbolAddress((void**)&d_agg, g_agg);
    uint32_t* d_W1t;  cudaGetSymbolAddress((void**)&d_W1t, g_W1t);
    uint32_t* d_W2t;  cudaGetSymbolAddress((void**)&d_W2t, g_W2t);

    // 1. zero agg + colsum
    {
        size_t total = (size_t)n_nodes * HIDDEN;
        int blocks = (int)((total + 511) / 512);
        if (blocks > 4096) blocks = 4096;
        zero_kernel<<<blocks, 512>>>(n_nodes);
    }

    // 1b. pre-convert weights
    wconv_kernel<<<8, 256>>>(W1, d_W1t);
    wconv_kernel<<<4, 256>>>(W2, d_W2t);

    // 2. scatter + edge_attr copy + colsum (x4 unrolled, single wave)
    {
        int blocks = 888;   // 148 SMs x 6 blocks (40 regs -> 6/SM), one wave
        if (idx64) {
            const long long* recv = (const long long*)edge_index + n_edges;
            scatter_copy_kernel<long long><<<blocks, 256>>>(
                (const float4*)edge_attr, recv, (float4*)out_ea, n_edges);
        } else {
            const int* recv = (const int*)edge_index + n_edges;
            scatter_copy_kernel<int><<<blocks, 256>>>(
                (const float4*)edge_attr, recv, (float4*)out_ea, n_edges);
        }
    }

    // 3. edge_index passthrough
    if (out_ei_f) {
        int n = 2 * n_edges;
        ei_copy_i32_as_float_kernel<<<(n + 255) / 256, 256>>>(
            (const int*)edge_index, out_ei_f, n);
    } else if (out_ei_raw) {
        int n = 2 * n_edges;
        ei_copy_raw64_kernel<<<(n + 255) / 256, 256>>>(
            (const long long*)edge_index, out_ei_raw, n);
    }

    // 4. fold column means into bias
    b1eff_kernel<<<HIDDEN, HIDDEN>>>(W1, b1, n_nodes);

    // 5. fused MLP
    {
        int smem_bytes = ARENA_WORDS * 4;
        cudaFuncSetAttribute(fused_mlp_kernel,
                             cudaFuncAttributeMaxDynamicSharedMemorySize,
                             smem_bytes);
        int blocks = (n_nodes + 127) / 128;
        fused_mlp_kernel<<<blocks, 256, smem_bytes>>>(node_attr, d_agg, b2,
                                                      out_x, n_nodes);
    }
}

// round 10
// speedup vs baseline: 1.0506x; 1.0506x over previous
#include <cuda_runtime.h>
#include <cuda_bf16.h>
#include <cstdint>

#define HIDDEN 128
#define MAX_NODES 50048
#define MAX_EDGES 800000

// ---------------- scratch (static device globals; no allocation) -------------
__device__ float    g_agg[(size_t)MAX_NODES * HIDDEN];
__device__ float    g_colsum[HIDDEN];
__device__ float    g_b1eff[HIDDEN];
__device__ uint32_t g_W1t[8 * 4096];
__device__ uint32_t g_W2t[4 * 4096];

// ---------------- kernel 1: zero agg + colsum (float4 stores) ----------------
__global__ void zero_kernel(int n_nodes) {
    size_t total4 = (size_t)n_nodes * (HIDDEN / 4);
    size_t i = (size_t)blockIdx.x * blockDim.x + threadIdx.x;
    size_t stride = (size_t)gridDim.x * blockDim.x;
    float4 z = make_float4(0.f, 0.f, 0.f, 0.f);
    float4* agg4 = (float4*)g_agg;
    for (size_t idx = i; idx < total4; idx += stride) agg4[idx] = z;
    if (i < HIDDEN) g_colsum[i] = 0.0f;
}

// ---------------- kernel 2: scatter + ea copy + ei copy + colsum -------------
// Round-8 config (best measured): x4 edge unroll, grid 1184, no min-blocks.
// ei passthrough fused in as a grid-stride prologue (independent traffic).
template<typename IDX>
__global__ void scatter_copy_kernel(const float4* __restrict__ ea,
                                    const IDX* __restrict__ recv,
                                    float4* __restrict__ out_ea,
                                    const IDX* __restrict__ ei,      // full 2 x E
                                    float* __restrict__ out_ei_f,    // i32 path
                                    long long* __restrict__ out_ei_raw, // i64 path
                                    int n_ei,                        // 2 x E
                                    int n_edges) {
    int tid  = blockIdx.x * blockDim.x + threadIdx.x;
    int nT   = gridDim.x * blockDim.x;

    // fused edge_index passthrough
    if (out_ei_f) {
        for (int i = tid; i < n_ei; i += nT)
            __stcs(&out_ei_f[i], (float)__ldcs(&((const int*)ei)[i]));
    } else if (out_ei_raw) {
        for (int i = tid; i < n_ei; i += nT)
            __stcs(&out_ei_raw[i], __ldcs(&((const long long*)ei)[i]));
    }

    int wl   = threadIdx.x >> 5;
    int lane = threadIdx.x & 31;
    int gw   = blockIdx.x * 8 + wl;
    int nW   = gridDim.x * 8;

    float4 acc = make_float4(0.f, 0.f, 0.f, 0.f);

    int e4_limit = n_edges & ~3;
    for (int e = gw * 4; e + 3 < e4_limit; e += nW * 4) {
        int r0 = (int)__ldcs(&recv[e + 0]);
        int r1 = (int)__ldcs(&recv[e + 1]);
        int r2 = (int)__ldcs(&recv[e + 2]);
        int r3 = (int)__ldcs(&recv[e + 3]);
        float4 v0 = __ldcs(&ea[(size_t)(e + 0) * 32 + lane]);
        float4 v1 = __ldcs(&ea[(size_t)(e + 1) * 32 + lane]);
        float4 v2 = __ldcs(&ea[(size_t)(e + 2) * 32 + lane]);
        float4 v3 = __ldcs(&ea[(size_t)(e + 3) * 32 + lane]);
        if (out_ea) {
            __stcs(&out_ea[(size_t)(e + 0) * 32 + lane], v0);
            __stcs(&out_ea[(size_t)(e + 1) * 32 + lane], v1);
            __stcs(&out_ea[(size_t)(e + 2) * 32 + lane], v2);
            __stcs(&out_ea[(size_t)(e + 3) * 32 + lane], v3);
        }
        acc.x += v0.x + v1.x + v2.x + v3.x;
        acc.y += v0.y + v1.y + v2.y + v3.y;
        acc.z += v0.z + v1.z + v2.z + v3.z;
        acc.w += v0.w + v1.w + v2.w + v3.w;
        float* d0 = g_agg + (size_t)r0 * HIDDEN + lane * 4;
        float* d1 = g_agg + (size_t)r1 * HIDDEN + lane * 4;
        float* d2 = g_agg + (size_t)r2 * HIDDEN + lane * 4;
        float* d3 = g_agg + (size_t)r3 * HIDDEN + lane * 4;
        asm volatile("red.global.add.v4.f32 [%0], {%1,%2,%3,%4};"
                     :: "l"(d0), "f"(v0.x), "f"(v0.y), "f"(v0.z), "f"(v0.w) : "memory");
        asm volatile("red.global.add.v4.f32 [%0], {%1,%2,%3,%4};"
                     :: "l"(d1), "f"(v1.x), "f"(v1.y), "f"(v1.z), "f"(v1.w) : "memory");
        asm volatile("red.global.add.v4.f32 [%0], {%1,%2,%3,%4};"
                     :: "l"(d2), "f"(v2.x), "f"(v2.y), "f"(v2.z), "f"(v2.w) : "memory");
        asm volatile("red.global.add.v4.f32 [%0], {%1,%2,%3,%4};"
                     :: "l"(d3), "f"(v3.x), "f"(v3.y), "f"(v3.z), "f"(v3.w) : "memory");
    }
    for (int e = e4_limit + gw; e < n_edges; e += nW) {
        int r = (int)__ldcs(&recv[e]);
        float4 v = __ldcs(&ea[(size_t)e * 32 + lane]);
        if (out_ea) __stcs(&out_ea[(size_t)e * 32 + lane], v);
        acc.x += v.x; acc.y += v.y; acc.z += v.z; acc.w += v.w;
        float* dst = g_agg + (size_t)r * HIDDEN + lane * 4;
        asm volatile("red.global.add.v4.f32 [%0], {%1,%2,%3,%4};"
                     :: "l"(dst), "f"(v.x), "f"(v.y), "f"(v.z), "f"(v.w) : "memory");
    }

    __shared__ float4 reds[8][32];
    reds[wl][lane] = acc;
    __syncthreads();
    if (wl == 0) {
        float4 s = reds[0][lane];
        #pragma unroll
        for (int w = 1; w < 8; w++) {
            float4 t = reds[w][lane];
            s.x += t.x; s.y += t.y; s.z += t.z; s.w += t.w;
        }
        atomicAdd(&g_colsum[lane * 4 + 0], s.x);
        atomicAdd(&g_colsum[lane * 4 + 1], s.y);
        atomicAdd(&g_colsum[lane * 4 + 2], s.z);
        atomicAdd(&g_colsum[lane * 4 + 3], s.w);
    }
}

// ---------------- kernel 4: fold mean into bias (parallel) -------------------
__global__ void b1eff_kernel(const float* __restrict__ W1,
                             const float* __restrict__ b1, int n_nodes) {
    int j = blockIdx.x;
    int k = threadIdx.x;
    float inv = 1.0f / (float)n_nodes;
    float v = g_colsum[k] * inv * __ldg(&W1[(size_t)(HIDDEN + k) * HIDDEN + j]);
    #pragma unroll
    for (int o = 16; o > 0; o >>= 1) v += __shfl_down_sync(0xffffffffu, v, o);
    __shared__ float red[4];
    if ((k & 31) == 0) red[k >> 5] = v;
    __syncthreads();
    if (k == 0)
        g_b1eff[j] = b1[j] - (red[0] + red[1] + red[2] + red[3]);
}

// ---------------- weight pre-convert -----------------------------------------
__device__ __forceinline__ uint32_t f2tf32(float f) {
    uint32_t u;
    asm("cvt.rna.tf32.f32 %0, %1;" : "=r"(u) : "f"(f));
    return u;
}

__global__ void wconv_kernel(const float* __restrict__ W,
                             uint32_t* __restrict__ out) {
    int t   = blockIdx.x;
    int tid = threadIdx.x;            // 256
    #pragma unroll
    for (int j = 0; j < 16; j++) {
        int o  = j * 256 + tid;
        int n  = o >> 5;
        int pk = o & 31;
        int k  = (pk & 7) * 4 + (pk >> 3);
        out[t * 4096 + o] = f2tf32(__ldg(&W[(size_t)(t * 32 + k) * HIDDEN + n]));
    }
}

// ---------------- fused 2-layer tf32 MLP -------------------------------------
#define SPAD 37
#define HS_W 4736
#define ARENA_WORDS 23936

__global__ void __launch_bounds__(256)
fused_mlp_kernel(const float* __restrict__ A0,
                 const float* __restrict__ A1,
                 const float* __restrict__ b2,
                 float* __restrict__ out, int n_rows) {
    extern __shared__ uint32_t sm[];
    uint32_t* Hs    = sm;
    uint32_t* As    = sm;
    uint32_t* Bs    = sm + HS_W;
    uint32_t* Bs2   = sm + 4 * HS_W;
    float*    sB1   = (float*)(sm + 23680);
    float*    sB2   = (float*)(sm + 23808);

    int tid  = threadIdx.x;
    int lane = tid & 31;
    int wid  = tid >> 5;
    int q    = lane & 3;
    int lg   = lane >> 2;
    int wm   = wid >> 2;
    int wn   = wid & 3;
    int Rw   = wm * 64;
    int Nw   = wn * 32;
    int row0 = blockIdx.x * 128;

    if (tid < HIDDEN) {
        sB1[tid] = g_b1eff[tid];
        sB2[tid] = b2[tid];
    }

    float c1[4][4][4];
    #pragma unroll
    for (int i = 0; i < 4; i++)
        #pragma unroll
        for (int j = 0; j < 4; j++)
            #pragma unroll
            for (int t = 0; t < 4; t++) c1[i][j][t] = 0.0f;

    float4 ar[4];
    uint4  br[4];

    {
        #pragma unroll
        for (int it = 0; it < 4; it++) {
            int idx = tid + it * 256;
            int row = idx >> 3, tt = idx & 7;
            int grow = row0 + row;
            ar[it] = (grow < n_rows)
                ? __ldg((const float4*)&A0[(size_t)grow * HIDDEN + tt * 4])
                : make_float4(0.f, 0.f, 0.f, 0.f);
        }
        const uint4* src = (const uint4*)g_W1t;
        #pragma unroll
        for (int j = 0; j < 4; j++) br[j] = __ldg(&src[j * 256 + tid]);
    }

    for (int t = 0; t < 8; t++) {
        #pragma unroll
        for (int it = 0; it < 4; it++) {
            int idx = tid + it * 256;
            int row = idx >> 3, tt = idx & 7;
            uint32_t* dst = &As[row * SPAD + tt];
            dst[0]  = f2tf32(ar[it].x);
            dst[8]  = f2tf32(ar[it].y);
            dst[16] = f2tf32(ar[it].z);
            dst[24] = f2tf32(ar[it].w);
        }
        #pragma unroll
        for (int j = 0; j < 4; j++) {
            int o  = (j * 256 + tid) * 4;
            int n  = o >> 5;
            int pk = o & 31;
            uint32_t* dst = &Bs[n * SPAD + pk];
            dst[0] = br[j].x; dst[1] = br[j].y;
            dst[2] = br[j].z; dst[3] = br[j].w;
        }
        __syncthreads();

        if (t < 7) {
            const float* Asrc = (t + 1 >= 4) ? A1 : A0;
            int kb = ((t + 1) & 3) * 32;
            #pragma unroll
            for (int it = 0; it < 4; it++) {
                int idx = tid + it * 256;
                int row = idx >> 3, tt = idx & 7;
                int grow = row0 + row;
                ar[it] = (grow < n_rows)
                    ? __ldg((const float4*)&Asrc[(size_t)grow * HIDDEN + kb + tt * 4])
                    : make_float4(0.f, 0.f, 0.f, 0.f);
            }
            const uint4* src = (const uint4*)&g_W1t[(t + 1) * 4096];
            #pragma unroll
            for (int j = 0; j < 4; j++) br[j] = __ldg(&src[j * 256 + tid]);
        }

        #pragma unroll
        for (int s = 0; s < 4; s++) {
            uint32_t a[4][4];
            #pragma unroll
            for (int mt = 0; mt < 4; mt++) {
                int r = Rw + mt * 16 + lg;
                int o0 = r * SPAD + q * 8 + 2 * s;
                int o1 = (r + 8) * SPAD + q * 8 + 2 * s;
                a[mt][0] = As[o0]; a[mt][2] = As[o0 + 1];
                a[mt][1] = As[o1]; a[mt][3] = As[o1 + 1];
            }
            uint32_t b[4][2];
            #pragma unroll
            for (int nt = 0; nt < 4; nt++) {
                int ob = (Nw + nt * 8 + lg) * SPAD + q * 8 + 2 * s;
                b[nt][0] = Bs[ob]; b[nt][1] = Bs[ob + 1];
            }
            #pragma unroll
            for (int mt = 0; mt < 4; mt++)
                #pragma unroll
                for (int nt = 0; nt < 4; nt++)
                    asm volatile(
                        "mma.sync.aligned.m16n8k8.row.col.f32.tf32.tf32.f32 "
                        "{%0,%1,%2,%3}, {%4,%5,%6,%7}, {%8,%9}, {%0,%1,%2,%3};"
                        : "+f"(c1[mt][nt][0]), "+f"(c1[mt][nt][1]),
                          "+f"(c1[mt][nt][2]), "+f"(c1[mt][nt][3])
                        : "r"(a[mt][0]), "r"(a[mt][1]),
                          "r"(a[mt][2]), "r"(a[mt][3]),
                          "r"(b[nt][0]), "r"(b[nt][1]));
        }
        __syncthreads();
    }

    // phase 2
    #pragma unroll
    for (int mt = 0; mt < 4; mt++) {
        int r0 = Rw + mt * 16 + lg;
        int r1 = r0 + 8;
        #pragma unroll
        for (int nt = 0; nt < 4; nt++) {
            int col = Nw + nt * 8 + 2 * q;
            int lk0 = nt * 8 + 2 * q;
            float bb0 = sB1[col], bb1 = sB1[col + 1];
            float v0 = fmaxf(c1[mt][nt][0] + bb0, 0.f);
            float v1 = fmaxf(c1[mt][nt][1] + bb1, 0.f);
            float v2 = fmaxf(c1[mt][nt][2] + bb0, 0.f);
            float v3 = fmaxf(c1[mt][nt][3] + bb1, 0.f);
            int p0 = (lk0 & 3) * 8 + (lk0 >> 2);
            int p1 = ((lk0 + 1) & 3) * 8 + ((lk0 + 1) >> 2);
            uint32_t* hb = &Hs[wn * HS_W];
            hb[r0 * SPAD + p0] = f2tf32(v0);
            hb[r0 * SPAD + p1] = f2tf32(v1);
            hb[r1 * SPAD + p0] = f2tf32(v2);
            hb[r1 * SPAD + p1] = f2tf32(v3);
        }
    }

    float c2[4][4][4];
    #pragma unroll
    for (int i = 0; i < 4; i++)
        #pragma unroll
        for (int j = 0; j < 4; j++)
            #pragma unroll
            for (int t = 0; t < 4; t++) c2[i][j][t] = 0.0f;

    {
        const uint4* src = (const uint4*)g_W2t;
        #pragma unroll
        for (int j = 0; j < 4; j++) br[j] = __ldg(&src[j * 256 + tid]);
    }

    for (int s = 0; s < 4; s++) {
        #pragma unroll
        for (int j = 0; j < 4; j++) {
            int o  = (j * 256 + tid) * 4;
            int n  = o >> 5;
            int pk = o & 31;
            uint32_t* dst = &Bs2[n * SPAD + pk];
            dst[0] = br[j].x; dst[1] = br[j].y;
            dst[2] = br[j].z; dst[3] = br[j].w;
        }
        __syncthreads();

        if (s < 3) {
            const uint4* src = (const uint4*)&g_W2t[(s + 1) * 4096];
            #pragma unroll
            for (int j = 0; j < 4; j++) br[j] = __ldg(&src[j * 256 + tid]);
        }

        const uint32_t* Hb = &Hs[s * HS_W];
        #pragma unroll
        for (int ss = 0; ss < 4; ss++) {
            uint32_t a[4][4];
            #pragma unroll
            for (int mt = 0; mt < 4; mt++) {
                int r = Rw + mt * 16 + lg;
                int o0 = r * SPAD + q * 8 + 2 * ss;
                int o1 = (r + 8) * SPAD + q * 8 + 2 * ss;
                a[mt][0] = Hb[o0]; a[mt][2] = Hb[o0 + 1];
                a[mt][1] = Hb[o1]; a[mt][3] = Hb[o1 + 1];
            }
            uint32_t b[4][2];
            #pragma unroll
            for (int nt = 0; nt < 4; nt++) {
                int ob = (Nw + nt * 8 + lg) * SPAD + q * 8 + 2 * ss;
                b[nt][0] = Bs2[ob]; b[nt][1] = Bs2[ob + 1];
            }
            #pragma unroll
            for (int mt = 0; mt < 4; mt++)
                #pragma unroll
                for (int nt = 0; nt < 4; nt++)
                    asm volatile(
                        "mma.sync.aligned.m16n8k8.row.col.f32.tf32.tf32.f32 "
                        "{%0,%1,%2,%3}, {%4,%5,%6,%7}, {%8,%9}, {%0,%1,%2,%3};"
                        : "+f"(c2[mt][nt][0]), "+f"(c2[mt][nt][1]),
                          "+f"(c2[mt][nt][2]), "+f"(c2[mt][nt][3])
                        : "r"(a[mt][0]), "r"(a[mt][1]),
                          "r"(a[mt][2]), "r"(a[mt][3]),
                          "r"(b[nt][0]), "r"(b[nt][1]));
        }
        __syncthreads();
    }

    #pragma unroll
    for (int mt = 0; mt < 4; mt++) {
        int r0g = row0 + Rw + mt * 16 + lg;
        int r1g = r0g + 8;
        #pragma unroll
        for (int nt = 0; nt < 4; nt++) {
            int col = Nw + nt * 8 + 2 * q;
            float bb0 = sB2[col], bb1 = sB2[col + 1];
            if (r0g < n_rows)
                *(float2*)&out[(size_t)r0g * HIDDEN + col] =
                    make_float2(c2[mt][nt][0] + bb0, c2[mt][nt][1] + bb1);
            if (r1g < n_rows)
                *(float2*)&out[(size_t)r1g * HIDDEN + col] =
                    make_float2(c2[mt][nt][2] + bb0, c2[mt][nt][3] + bb1);
        }
    }
}

// ---------------- launcher ---------------------------------------------------
extern "C" void kernel_launch(void* const* d_in, const int* in_sizes, int n_in,
                              void* d_out, int out_size) {
    const float* node_attr  = (const float*)d_in[0];
    const void*  edge_index = d_in[1];
    const float* edge_attr  = (const float*)d_in[2];
    const float* W1         = (const float*)d_in[3];
    const float* b1         = (const float*)d_in[4];
    const float* W2         = (const float*)d_in[5];
    const float* b2         = (const float*)d_in[6];

    int n_nodes = in_sizes[0] / HIDDEN;
    int n_edges = in_sizes[1] / 2;

    size_t x_el  = (size_t)n_nodes * HIDDEN;
    size_t ei_el = 2 * (size_t)n_edges;
    size_t ea_el = (size_t)n_edges * HIDDEN;

    float* out   = (float*)d_out;
    float* out_x = out;

    size_t os = (size_t)out_size;
    bool idx64 = false;
    float*     out_ei_f   = nullptr;
    long long* out_ei_raw = nullptr;
    float*     out_ea     = nullptr;
    if (os == x_el + ei_el + ea_el) {
        idx64 = false;
        out_ei_f = out + x_el;
        out_ea   = out + x_el + ei_el;
    } else if (os == x_el + 2 * ei_el + ea_el) {
        idx64 = true;
        out_ei_raw = (long long*)(out + x_el);
        out_ea     = out + x_el + 2 * ei_el;
    }

    float*    d_agg;  cudaGetSymbolAddress((void**)&d_agg, g_agg);
    uint32_t* d_W1t;  cudaGetSymbolAddress((void**)&d_W1t, g_W1t);
    uint32_t* d_W2t;  cudaGetSymbolAddress((void**)&d_W2t, g_W2t);

    // 1. zero agg + colsum (float4)
    {
        size_t total4 = (size_t)n_nodes * (HIDDEN / 4);
        int blocks = (int)((total4 + 511) / 512);
        if (blocks > 2048) blocks = 2048;
        zero_kernel<<<blocks, 512>>>(n_nodes);
    }

    // 1b. pre-convert weights
    wconv_kernel<<<8, 256>>>(W1, d_W1t);
    wconv_kernel<<<4, 256>>>(W2, d_W2t);

    // 2. scatter + ea copy + ei copy + colsum (round-8 grid: 1184)
    {
        int blocks = 1184;
        int n_ei = 2 * n_edges;
        if (idx64) {
            const long long* eil = (const long long*)edge_index;
            scatter_copy_kernel<long long><<<blocks, 256>>>(
                (const float4*)edge_attr, eil + n_edges, (float4*)out_ea,
                eil, nullptr, out_ei_raw, n_ei, n_edges);
        } else {
            const int* eii = (const int*)edge_index;
            scatter_copy_kernel<int><<<blocks, 256>>>(
                (const float4*)edge_attr, eii + n_edges, (float4*)out_ea,
                eii, out_ei_f, nullptr, n_ei, n_edges);
        }
    }

    // 3. fold column means into bias
    b1eff_kernel<<<HIDDEN, HIDDEN>>>(W1, b1, n_nodes);

    // 4. fused MLP
    {
        int smem_bytes = ARENA_WORDS * 4;
        cudaFuncSetAttribute(fused_mlp_kernel,
                             cudaFuncAttributeMaxDynamicSharedMemorySize,
                             smem_bytes);
        int blocks = (n_nodes + 127) / 128;
        fused_mlp_kernel<<<blocks, 256, smem_bytes>>>(node_attr, d_agg, b2,
                                                      out_x, n_nodes);
    }
}

// round 11
// speedup vs baseline: 1.0931x; 1.0405x over previous
#include <cuda_runtime.h>
#include <cuda_bf16.h>
#include <cstdint>

#define HIDDEN 128
#define MAX_NODES 50048
#define MAX_EDGES 800000

// ---------------- scratch (static device globals; no allocation) -------------
__device__ float    g_agg[(size_t)MAX_NODES * HIDDEN];
__device__ float    g_colsum[HIDDEN];
__device__ float    g_b1eff[HIDDEN];
__device__ uint32_t g_W1t[8 * 4096];
__device__ uint32_t g_W2t[4 * 4096];

__device__ __forceinline__ uint32_t f2tf32(float f) {
    uint32_t u;
    asm("cvt.rna.tf32.f32 %0, %1;" : "=r"(u) : "f"(f));
    return u;
}

// ---------------- kernel 1: fused init (zero agg+colsum, wconv W1/W2) --------
// blocks [0,12): weight tiles (8 W1 + 4 W2). blocks [12,...): zero agg.
__global__ void __launch_bounds__(256)
init_kernel(const float* __restrict__ W1, const float* __restrict__ W2,
            int n_nodes) {
    int b   = blockIdx.x;
    int tid = threadIdx.x;
    if (b < 12) {
        const float* W = (b < 8) ? W1 : W2;
        uint32_t*    o = (b < 8) ? g_W1t : g_W2t;
        int t = (b < 8) ? b : b - 8;
        #pragma unroll
        for (int j = 0; j < 16; j++) {
            int oo = j * 256 + tid;
            int n  = oo >> 5;
            int pk = oo & 31;
            int k  = (pk & 7) * 4 + (pk >> 3);
            o[t * 4096 + oo] =
                f2tf32(__ldg(&W[(size_t)(t * 32 + k) * HIDDEN + n]));
        }
        if (b == 0 && tid < HIDDEN) g_colsum[tid] = 0.0f;
    } else {
        size_t total4 = (size_t)n_nodes * (HIDDEN / 4);
        size_t i      = (size_t)(b - 12) * 256 + tid;
        size_t stride = (size_t)(gridDim.x - 12) * 256;
        float4 z = make_float4(0.f, 0.f, 0.f, 0.f);
        float4* agg4 = (float4*)g_agg;
        for (size_t idx = i; idx < total4; idx += stride) agg4[idx] = z;
    }
}

// ---------------- kernel 2: scatter + ea copy + ei copy + colsum -------------
// x8 edge unroll, vectorized index loads, 4 blocks/SM (64-reg cap).
__device__ __forceinline__ void load8_idx(const int* __restrict__ recv,
                                          int e, int r[8]) {
    int4 a = __ldcs((const int4*)(recv + e));
    int4 b = __ldcs((const int4*)(recv + e + 4));
    r[0] = a.x; r[1] = a.y; r[2] = a.z; r[3] = a.w;
    r[4] = b.x; r[5] = b.y; r[6] = b.z; r[7] = b.w;
}
__device__ __forceinline__ void load8_idx(const long long* __restrict__ recv,
                                          int e, int r[8]) {
    #pragma unroll
    for (int i = 0; i < 8; i++) r[i] = (int)__ldcs(&recv[e + i]);
}

template<typename IDX>
__global__ void __launch_bounds__(256, 4)
scatter_copy_kernel(const float4* __restrict__ ea,
                    const IDX* __restrict__ recv,
                    float4* __restrict__ out_ea,
                    const IDX* __restrict__ ei,
                    float* __restrict__ out_ei_f,
                    long long* __restrict__ out_ei_raw,
                    int n_ei,
                    int n_edges) {
    int tid  = blockIdx.x * blockDim.x + threadIdx.x;
    int nT   = gridDim.x * blockDim.x;

    // fused edge_index passthrough
    if (out_ei_f) {
        for (int i = tid; i < n_ei; i += nT)
            __stcs(&out_ei_f[i], (float)__ldcs(&((const int*)ei)[i]));
    } else if (out_ei_raw) {
        for (int i = tid; i < n_ei; i += nT)
            __stcs(&out_ei_raw[i], __ldcs(&((const long long*)ei)[i]));
    }

    int wl   = threadIdx.x >> 5;
    int lane = threadIdx.x & 31;
    int gw   = blockIdx.x * 8 + wl;
    int nW   = gridDim.x * 8;

    float4 acc = make_float4(0.f, 0.f, 0.f, 0.f);

    int e8 = n_edges & ~7;
    for (int e = gw * 8; e + 7 < e8; e += nW * 8) {
        int r[8];
        load8_idx(recv, e, r);
        float4 v[8];
        #pragma unroll
        for (int i = 0; i < 8; i++)
            v[i] = __ldcs(&ea[(size_t)(e + i) * 32 + lane]);
        if (out_ea) {
            #pragma unroll
            for (int i = 0; i < 8; i++)
                __stcs(&out_ea[(size_t)(e + i) * 32 + lane], v[i]);
        }
        #pragma unroll
        for (int i = 0; i < 8; i++) {
            acc.x += v[i].x; acc.y += v[i].y;
            acc.z += v[i].z; acc.w += v[i].w;
        }
        #pragma unroll
        for (int i = 0; i < 8; i++) {
            float* d = g_agg + (size_t)r[i] * HIDDEN + lane * 4;
            asm volatile("red.global.add.v4.f32 [%0], {%1,%2,%3,%4};"
                         :: "l"(d), "f"(v[i].x), "f"(v[i].y),
                            "f"(v[i].z), "f"(v[i].w) : "memory");
        }
    }
    // tail
    for (int e = e8 + gw; e < n_edges; e += nW) {
        int r = (int)__ldcs(&recv[e]);
        float4 v = __ldcs(&ea[(size_t)e * 32 + lane]);
        if (out_ea) __stcs(&out_ea[(size_t)e * 32 + lane], v);
        acc.x += v.x; acc.y += v.y; acc.z += v.z; acc.w += v.w;
        float* dst = g_agg + (size_t)r * HIDDEN + lane * 4;
        asm volatile("red.global.add.v4.f32 [%0], {%1,%2,%3,%4};"
                     :: "l"(dst), "f"(v.x), "f"(v.y), "f"(v.z), "f"(v.w)
                     : "memory");
    }

    __shared__ float4 reds[8][32];
    reds[wl][lane] = acc;
    __syncthreads();
    if (wl == 0) {
        float4 s = reds[0][lane];
        #pragma unroll
        for (int w = 1; w < 8; w++) {
            float4 t = reds[w][lane];
            s.x += t.x; s.y += t.y; s.z += t.z; s.w += t.w;
        }
        atomicAdd(&g_colsum[lane * 4 + 0], s.x);
        atomicAdd(&g_colsum[lane * 4 + 1], s.y);
        atomicAdd(&g_colsum[lane * 4 + 2], s.z);
        atomicAdd(&g_colsum[lane * 4 + 3], s.w);
    }
}

// ---------------- kernel 3: fold mean into bias (parallel) -------------------
__global__ void b1eff_kernel(const float* __restrict__ W1,
                             const float* __restrict__ b1, int n_nodes) {
    int j = blockIdx.x;
    int k = threadIdx.x;
    float inv = 1.0f / (float)n_nodes;
    float v = g_colsum[k] * inv * __ldg(&W1[(size_t)(HIDDEN + k) * HIDDEN + j]);
    #pragma unroll
    for (int o = 16; o > 0; o >>= 1) v += __shfl_down_sync(0xffffffffu, v, o);
    __shared__ float red[4];
    if ((k & 31) == 0) red[k >> 5] = v;
    __syncthreads();
    if (k == 0)
        g_b1eff[j] = b1[j] - (red[0] + red[1] + red[2] + red[3]);
}

// ---------------- fused 2-layer tf32 MLP -------------------------------------
#define SPAD 37
#define HS_W 4736
#define ARENA_WORDS 23936

__global__ void __launch_bounds__(256)
fused_mlp_kernel(const float* __restrict__ A0,
                 const float* __restrict__ A1,
                 const float* __restrict__ b2,
                 float* __restrict__ out, int n_rows) {
    extern __shared__ uint32_t sm[];
    uint32_t* Hs    = sm;
    uint32_t* As    = sm;
    uint32_t* Bs    = sm + HS_W;
    uint32_t* Bs2   = sm + 4 * HS_W;
    float*    sB1   = (float*)(sm + 23680);
    float*    sB2   = (float*)(sm + 23808);

    int tid  = threadIdx.x;
    int lane = tid & 31;
    int wid  = tid >> 5;
    int q    = lane & 3;
    int lg   = lane >> 2;
    int wm   = wid >> 2;
    int wn   = wid & 3;
    int Rw   = wm * 64;
    int Nw   = wn * 32;
    int row0 = blockIdx.x * 128;

    if (tid < HIDDEN) {
        sB1[tid] = g_b1eff[tid];
        sB2[tid] = b2[tid];
    }

    float c1[4][4][4];
    #pragma unroll
    for (int i = 0; i < 4; i++)
        #pragma unroll
        for (int j = 0; j < 4; j++)
            #pragma unroll
            for (int t = 0; t < 4; t++) c1[i][j][t] = 0.0f;

    float4 ar[4];
    uint4  br[4];

    {
        #pragma unroll
        for (int it = 0; it < 4; it++) {
            int idx = tid + it * 256;
            int row = idx >> 3, tt = idx & 7;
            int grow = row0 + row;
            ar[it] = (grow < n_rows)
                ? __ldg((const float4*)&A0[(size_t)grow * HIDDEN + tt * 4])
                : make_float4(0.f, 0.f, 0.f, 0.f);
        }
        const uint4* src = (const uint4*)g_W1t;
        #pragma unroll
        for (int j = 0; j < 4; j++) br[j] = __ldg(&src[j * 256 + tid]);
    }

    for (int t = 0; t < 8; t++) {
        #pragma unroll
        for (int it = 0; it < 4; it++) {
            int idx = tid + it * 256;
            int row = idx >> 3, tt = idx & 7;
            uint32_t* dst = &As[row * SPAD + tt];
            dst[0]  = f2tf32(ar[it].x);
            dst[8]  = f2tf32(ar[it].y);
            dst[16] = f2tf32(ar[it].z);
            dst[24] = f2tf32(ar[it].w);
        }
        #pragma unroll
        for (int j = 0; j < 4; j++) {
            int o  = (j * 256 + tid) * 4;
            int n  = o >> 5;
            int pk = o & 31;
            uint32_t* dst = &Bs[n * SPAD + pk];
            dst[0] = br[j].x; dst[1] = br[j].y;
            dst[2] = br[j].z; dst[3] = br[j].w;
        }
        __syncthreads();

        if (t < 7) {
            const float* Asrc = (t + 1 >= 4) ? A1 : A0;
            int kb = ((t + 1) & 3) * 32;
            #pragma unroll
            for (int it = 0; it < 4; it++) {
                int idx = tid + it * 256;
                int row = idx >> 3, tt = idx & 7;
                int grow = row0 + row;
                ar[it] = (grow < n_rows)
                    ? __ldg((const float4*)&Asrc[(size_t)grow * HIDDEN + kb + tt * 4])
                    : make_float4(0.f, 0.f, 0.f, 0.f);
            }
            const uint4* src = (const uint4*)&g_W1t[(t + 1) * 4096];
            #pragma unroll
            for (int j = 0; j < 4; j++) br[j] = __ldg(&src[j * 256 + tid]);
        }

        #pragma unroll
        for (int s = 0; s < 4; s++) {
            uint32_t a[4][4];
            #pragma unroll
            for (int mt = 0; mt < 4; mt++) {
                int r = Rw + mt * 16 + lg;
                int o0 = r * SPAD + q * 8 + 2 * s;
                int o1 = (r + 8) * SPAD + q * 8 + 2 * s;
                a[mt][0] = As[o0]; a[mt][2] = As[o0 + 1];
                a[mt][1] = As[o1]; a[mt][3] = As[o1 + 1];
            }
            uint32_t b[4][2];
            #pragma unroll
            for (int nt = 0; nt < 4; nt++) {
                int ob = (Nw + nt * 8 + lg) * SPAD + q * 8 + 2 * s;
                b[nt][0] = Bs[ob]; b[nt][1] = Bs[ob + 1];
            }
            #pragma unroll
            for (int mt = 0; mt < 4; mt++)
                #pragma unroll
                for (int nt = 0; nt < 4; nt++)
                    asm volatile(
                        "mma.sync.aligned.m16n8k8.row.col.f32.tf32.tf32.f32 "
                        "{%0,%1,%2,%3}, {%4,%5,%6,%7}, {%8,%9}, {%0,%1,%2,%3};"
                        : "+f"(c1[mt][nt][0]), "+f"(c1[mt][nt][1]),
                          "+f"(c1[mt][nt][2]), "+f"(c1[mt][nt][3])
                        : "r"(a[mt][0]), "r"(a[mt][1]),
                          "r"(a[mt][2]), "r"(a[mt][3]),
                          "r"(b[nt][0]), "r"(b[nt][1]));
        }
        __syncthreads();
    }

    // phase 2
    #pragma unroll
    for (int mt = 0; mt < 4; mt++) {
        int r0 = Rw + mt * 16 + lg;
        int r1 = r0 + 8;
        #pragma unroll
        for (int nt = 0; nt < 4; nt++) {
            int col = Nw + nt * 8 + 2 * q;
            int lk0 = nt * 8 + 2 * q;
            float bb0 = sB1[col], bb1 = sB1[col + 1];
            float v0 = fmaxf(c1[mt][nt][0] + bb0, 0.f);
            float v1 = fmaxf(c1[mt][nt][1] + bb1, 0.f);
            float v2 = fmaxf(c1[mt][nt][2] + bb0, 0.f);
            float v3 = fmaxf(c1[mt][nt][3] + bb1, 0.f);
            int p0 = (lk0 & 3) * 8 + (lk0 >> 2);
            int p1 = ((lk0 + 1) & 3) * 8 + ((lk0 + 1) >> 2);
            uint32_t* hb = &Hs[wn * HS_W];
            hb[r0 * SPAD + p0] = f2tf32(v0);
            hb[r0 * SPAD + p1] = f2tf32(v1);
            hb[r1 * SPAD + p0] = f2tf32(v2);
            hb[r1 * SPAD + p1] = f2tf32(v3);
        }
    }

    float c2[4][4][4];
    #pragma unroll
    for (int i = 0; i < 4; i++)
        #pragma unroll
        for (int j = 0; j < 4; j++)
            #pragma unroll
            for (int t = 0; t < 4; t++) c2[i][j][t] = 0.0f;

    {
        const uint4* src = (const uint4*)g_W2t;
        #pragma unroll
        for (int j = 0; j < 4; j++) br[j] = __ldg(&src[j * 256 + tid]);
    }

    for (int s = 0; s < 4; s++) {
        #pragma unroll
        for (int j = 0; j < 4; j++) {
            int o  = (j * 256 + tid) * 4;
            int n  = o >> 5;
            int pk = o & 31;
            uint32_t* dst = &Bs2[n * SPAD + pk];
            dst[0] = br[j].x; dst[1] = br[j].y;
            dst[2] = br[j].z; dst[3] = br[j].w;
        }
        __syncthreads();

        if (s < 3) {
            const uint4* src = (const uint4*)&g_W2t[(s + 1) * 4096];
            #pragma unroll
            for (int j = 0; j < 4; j++) br[j] = __ldg(&src[j * 256 + tid]);
        }

        const uint32_t* Hb = &Hs[s * HS_W];
        #pragma unroll
        for (int ss = 0; ss < 4; ss++) {
            uint32_t a[4][4];
            #pragma unroll
            for (int mt = 0; mt < 4; mt++) {
                int r = Rw + mt * 16 + lg;
                int o0 = r * SPAD + q * 8 + 2 * ss;
                int o1 = (r + 8) * SPAD + q * 8 + 2 * ss;
                a[mt][0] = Hb[o0]; a[mt][2] = Hb[o0 + 1];
                a[mt][1] = Hb[o1]; a[mt][3] = Hb[o1 + 1];
            }
            uint32_t b[4][2];
            #pragma unroll
            for (int nt = 0; nt < 4; nt++) {
                int ob = (Nw + nt * 8 + lg) * SPAD + q * 8 + 2 * ss;
                b[nt][0] = Bs2[ob]; b[nt][1] = Bs2[ob + 1];
            }
            #pragma unroll
            for (int mt = 0; mt < 4; mt++)
                #pragma unroll
                for (int nt = 0; nt < 4; nt++)
                    asm volatile(
                        "mma.sync.aligned.m16n8k8.row.col.f32.tf32.tf32.f32 "
                        "{%0,%1,%2,%3}, {%4,%5,%6,%7}, {%8,%9}, {%0,%1,%2,%3};"
                        : "+f"(c2[mt][nt][0]), "+f"(c2[mt][nt][1]),
                          "+f"(c2[mt][nt][2]), "+f"(c2[mt][nt][3])
                        : "r"(a[mt][0]), "r"(a[mt][1]),
                          "r"(a[mt][2]), "r"(a[mt][3]),
                          "r"(b[nt][0]), "r"(b[nt][1]));
        }
        __syncthreads();
    }

    #pragma unroll
    for (int mt = 0; mt < 4; mt++) {
        int r0g = row0 + Rw + mt * 16 + lg;
        int r1g = r0g + 8;
        #pragma unroll
        for (int nt = 0; nt < 4; nt++) {
            int col = Nw + nt * 8 + 2 * q;
            float bb0 = sB2[col], bb1 = sB2[col + 1];
            if (r0g < n_rows)
                *(float2*)&out[(size_t)r0g * HIDDEN + col] =
                    make_float2(c2[mt][nt][0] + bb0, c2[mt][nt][1] + bb1);
            if (r1g < n_rows)
                *(float2*)&out[(size_t)r1g * HIDDEN + col] =
                    make_float2(c2[mt][nt][2] + bb0, c2[mt][nt][3] + bb1);
        }
    }
}

// ---------------- launcher ---------------------------------------------------
extern "C" void kernel_launch(void* const* d_in, const int* in_sizes, int n_in,
                              void* d_out, int out_size) {
    const float* node_attr  = (const float*)d_in[0];
    const void*  edge_index = d_in[1];
    const float* edge_attr  = (const float*)d_in[2];
    const float* W1         = (const float*)d_in[3];
    const float* b1         = (const float*)d_in[4];
    const float* W2         = (const float*)d_in[5];
    const float* b2         = (const float*)d_in[6];

    int n_nodes = in_sizes[0] / HIDDEN;
    int n_edges = in_sizes[1] / 2;

    size_t x_el  = (size_t)n_nodes * HIDDEN;
    size_t ei_el = 2 * (size_t)n_edges;
    size_t ea_el = (size_t)n_edges * HIDDEN;

    float* out   = (float*)d_out;
    float* out_x = out;

    size_t os = (size_t)out_size;
    bool idx64 = false;
    float*     out_ei_f   = nullptr;
    long long* out_ei_raw = nullptr;
    float*     out_ea     = nullptr;
    if (os == x_el + ei_el + ea_el) {
        idx64 = false;
        out_ei_f = out + x_el;
        out_ea   = out + x_el + ei_el;
    } else if (os == x_el + 2 * ei_el + ea_el) {
        idx64 = true;
        out_ei_raw = (long long*)(out + x_el);
        out_ea     = out + x_el + 2 * ei_el;
    }

    float* d_agg; cudaGetSymbolAddress((void**)&d_agg, g_agg);

    // 1. fused init: wconv (blocks 0-11) + zero agg (blocks 12+)
    init_kernel<<<2060, 256>>>(W1, W2, n_nodes);

    // 2. scatter + ea copy + ei copy + colsum (x8 unroll, 4 blocks/SM)
    {
        int blocks = 1184;
        int n_ei = 2 * n_edges;
        if (idx64) {
            const long long* eil = (const long long*)edge_index;
            scatter_copy_kernel<long long><<<blocks, 256>>>(
                (const float4*)edge_attr, eil + n_edges, (float4*)out_ea,
                eil, nullptr, out_ei_raw, n_ei, n_edges);
        } else {
            const int* eii = (const int*)edge_index;
            scatter_copy_kernel<int><<<blocks, 256>>>(
                (const float4*)edge_attr, eii + n_edges, (float4*)out_ea,
                eii, out_ei_f, nullptr, n_ei, n_edges);
        }
    }

    // 3. fold column means into bias
    b1eff_kernel<<<HIDDEN, HIDDEN>>>(W1, b1, n_nodes);

    // 4. fused MLP
    {
        int smem_bytes = ARENA_WORDS * 4;
        cudaFuncSetAttribute(fused_mlp_kernel,
                             cudaFuncAttributeMaxDynamicSharedMemorySize,
                             smem_bytes);
        int blocks = (n_nodes + 127) / 128;
        fused_mlp_kernel<<<blocks, 256, smem_bytes>>>(node_attr, d_agg, b2,
                                                      out_x, n_nodes);
    }
}

// round 12
// speedup vs baseline: 1.0977x; 1.0042x over previous
#include <cuda_runtime.h>
#include <cuda_bf16.h>
#include <cstdint>

#define HIDDEN 128
#define MAX_NODES 50048
#define MAX_EDGES 800000

// ---------------- scratch (static device globals; no allocation) -------------
__device__ float    g_agg[(size_t)MAX_NODES * HIDDEN];
__device__ float    g_colsum[HIDDEN];
__device__ float    g_b1eff[HIDDEN];
__device__ uint32_t g_W1t[8 * 4096];
__device__ uint32_t g_W2t[4 * 4096];

__device__ __forceinline__ uint32_t f2tf32(float f) {
    uint32_t u;
    asm("cvt.rna.tf32.f32 %0, %1;" : "=r"(u) : "f"(f));
    return u;
}

// ---------------- kernel 1: fused init (zero agg+colsum, wconv W1/W2) --------
__global__ void __launch_bounds__(256)
init_kernel(const float* __restrict__ W1, const float* __restrict__ W2,
            int n_nodes) {
    int b   = blockIdx.x;
    int tid = threadIdx.x;
    if (b < 12) {
        const float* W = (b < 8) ? W1 : W2;
        uint32_t*    o = (b < 8) ? g_W1t : g_W2t;
        int t = (b < 8) ? b : b - 8;
        #pragma unroll
        for (int j = 0; j < 16; j++) {
            int oo = j * 256 + tid;
            int n  = oo >> 5;
            int pk = oo & 31;
            int k  = (pk & 7) * 4 + (pk >> 3);
            o[t * 4096 + oo] =
                f2tf32(__ldg(&W[(size_t)(t * 32 + k) * HIDDEN + n]));
        }
        if (b == 0 && tid < HIDDEN) g_colsum[tid] = 0.0f;
    } else {
        size_t total4 = (size_t)n_nodes * (HIDDEN / 4);
        size_t i      = (size_t)(b - 12) * 256 + tid;
        size_t stride = (size_t)(gridDim.x - 12) * 256;
        float4 z = make_float4(0.f, 0.f, 0.f, 0.f);
        float4* agg4 = (float4*)g_agg;
        for (size_t idx = i; idx < total4; idx += stride) agg4[idx] = z;
    }
}

// ---------------- kernel 2: scatter + ea copy + ei copy + colsum -------------
__device__ __forceinline__ void load8_idx(const int* __restrict__ recv,
                                          int e, int r[8]) {
    int4 a = __ldcs((const int4*)(recv + e));
    int4 b = __ldcs((const int4*)(recv + e + 4));
    r[0] = a.x; r[1] = a.y; r[2] = a.z; r[3] = a.w;
    r[4] = b.x; r[5] = b.y; r[6] = b.z; r[7] = b.w;
}
__device__ __forceinline__ void load8_idx(const long long* __restrict__ recv,
                                          int e, int r[8]) {
    #pragma unroll
    for (int i = 0; i < 8; i++) r[i] = (int)__ldcs(&recv[e + i]);
}

template<typename IDX>
__global__ void __launch_bounds__(256, 4)
scatter_copy_kernel(const float4* __restrict__ ea,
                    const IDX* __restrict__ recv,
                    float4* __restrict__ out_ea,
                    const IDX* __restrict__ ei,
                    float* __restrict__ out_ei_f,
                    long long* __restrict__ out_ei_raw,
                    int n_ei,
                    int n_edges) {
    int tid  = blockIdx.x * blockDim.x + threadIdx.x;
    int nT   = gridDim.x * blockDim.x;

    if (out_ei_f) {
        for (int i = tid; i < n_ei; i += nT)
            __stcs(&out_ei_f[i], (float)__ldcs(&((const int*)ei)[i]));
    } else if (out_ei_raw) {
        for (int i = tid; i < n_ei; i += nT)
            __stcs(&out_ei_raw[i], __ldcs(&((const long long*)ei)[i]));
    }

    int wl   = threadIdx.x >> 5;
    int lane = threadIdx.x & 31;
    int gw   = blockIdx.x * 8 + wl;
    int nW   = gridDim.x * 8;

    float4 acc = make_float4(0.f, 0.f, 0.f, 0.f);

    int e8 = n_edges & ~7;
    for (int e = gw * 8; e + 7 < e8; e += nW * 8) {
        int r[8];
        load8_idx(recv, e, r);
        float4 v[8];
        #pragma unroll
        for (int i = 0; i < 8; i++)
            v[i] = __ldcs(&ea[(size_t)(e + i) * 32 + lane]);
        if (out_ea) {
            #pragma unroll
            for (int i = 0; i < 8; i++)
                __stcs(&out_ea[(size_t)(e + i) * 32 + lane], v[i]);
        }
        #pragma unroll
        for (int i = 0; i < 8; i++) {
            acc.x += v[i].x; acc.y += v[i].y;
            acc.z += v[i].z; acc.w += v[i].w;
        }
        #pragma unroll
        for (int i = 0; i < 8; i++) {
            float* d = g_agg + (size_t)r[i] * HIDDEN + lane * 4;
            asm volatile("red.global.add.v4.f32 [%0], {%1,%2,%3,%4};"
                         :: "l"(d), "f"(v[i].x), "f"(v[i].y),
                            "f"(v[i].z), "f"(v[i].w) : "memory");
        }
    }
    for (int e = e8 + gw; e < n_edges; e += nW) {
        int r = (int)__ldcs(&recv[e]);
        float4 v = __ldcs(&ea[(size_t)e * 32 + lane]);
        if (out_ea) __stcs(&out_ea[(size_t)e * 32 + lane], v);
        acc.x += v.x; acc.y += v.y; acc.z += v.z; acc.w += v.w;
        float* dst = g_agg + (size_t)r * HIDDEN + lane * 4;
        asm volatile("red.global.add.v4.f32 [%0], {%1,%2,%3,%4};"
                     :: "l"(dst), "f"(v.x), "f"(v.y), "f"(v.z), "f"(v.w)
                     : "memory");
    }

    __shared__ float4 reds[8][32];
    reds[wl][lane] = acc;
    __syncthreads();
    if (wl == 0) {
        float4 s = reds[0][lane];
        #pragma unroll
        for (int w = 1; w < 8; w++) {
            float4 t = reds[w][lane];
            s.x += t.x; s.y += t.y; s.z += t.z; s.w += t.w;
        }
        atomicAdd(&g_colsum[lane * 4 + 0], s.x);
        atomicAdd(&g_colsum[lane * 4 + 1], s.y);
        atomicAdd(&g_colsum[lane * 4 + 2], s.z);
        atomicAdd(&g_colsum[lane * 4 + 3], s.w);
    }
}

// ---------------- kernel 3: fold mean into bias (parallel) -------------------
__global__ void b1eff_kernel(const float* __restrict__ W1,
                             const float* __restrict__ b1, int n_nodes) {
    int j = blockIdx.x;
    int k = threadIdx.x;
    float inv = 1.0f / (float)n_nodes;
    float v = g_colsum[k] * inv * __ldg(&W1[(size_t)(HIDDEN + k) * HIDDEN + j]);
    #pragma unroll
    for (int o = 16; o > 0; o >>= 1) v += __shfl_down_sync(0xffffffffu, v, o);
    __shared__ float red[4];
    if ((k & 31) == 0) red[k >> 5] = v;
    __syncthreads();
    if (k == 0)
        g_b1eff[j] = b1[j] - (red[0] + red[1] + red[2] + red[3]);
}

// ---------------- fused 2-layer tf32 MLP, 512 threads ------------------------
// 16 warps = 4 M x 4 N, warp tile 32x32, block tile 128x128.
// c1/c2 shrink to 32 floats/warp -> ~half the registers of the 256-thr version.
#define SPAD 37
#define HS_W 4736
#define ARENA_WORDS 23936

__global__ void __launch_bounds__(512)
fused_mlp_kernel(const float* __restrict__ A0,
                 const float* __restrict__ A1,
                 const float* __restrict__ b2,
                 float* __restrict__ out, int n_rows) {
    extern __shared__ uint32_t sm[];
    uint32_t* Hs    = sm;
    uint32_t* As    = sm;
    uint32_t* Bs    = sm + HS_W;
    uint32_t* Bs2   = sm + 4 * HS_W;
    float*    sB1   = (float*)(sm + 23680);
    float*    sB2   = (float*)(sm + 23808);

    int tid  = threadIdx.x;            // 0..511
    int lane = tid & 31;
    int wid  = tid >> 5;               // 0..15
    int q    = lane & 3;
    int lg   = lane >> 2;
    int wm   = wid >> 2;               // 0..3 : 32 rows each
    int wn   = wid & 3;                // 0..3 : 32 cols each
    int Rw   = wm * 32;
    int Nw   = wn * 32;
    int row0 = blockIdx.x * 128;

    if (tid < HIDDEN) {
        sB1[tid] = g_b1eff[tid];
        sB2[tid] = b2[tid];
    }

    float c1[2][4][4];
    #pragma unroll
    for (int i = 0; i < 2; i++)
        #pragma unroll
        for (int j = 0; j < 4; j++)
            #pragma unroll
            for (int t = 0; t < 4; t++) c1[i][j][t] = 0.0f;

    float4 ar[2];
    uint4  br[2];

    {
        #pragma unroll
        for (int it = 0; it < 2; it++) {
            int idx = tid + it * 512;
            int row = idx >> 3, tt = idx & 7;
            int grow = row0 + row;
            ar[it] = (grow < n_rows)
                ? __ldg((const float4*)&A0[(size_t)grow * HIDDEN + tt * 4])
                : make_float4(0.f, 0.f, 0.f, 0.f);
        }
        const uint4* src = (const uint4*)g_W1t;
        #pragma unroll
        for (int j = 0; j < 2; j++) br[j] = __ldg(&src[j * 512 + tid]);
    }

    // ---------------- phase 1: c1 = [A0|A1] @ W1 -----------------------------
    for (int t = 0; t < 8; t++) {
        #pragma unroll
        for (int it = 0; it < 2; it++) {
            int idx = tid + it * 512;
            int row = idx >> 3, tt = idx & 7;
            uint32_t* dst = &As[row * SPAD + tt];
            dst[0]  = f2tf32(ar[it].x);
            dst[8]  = f2tf32(ar[it].y);
            dst[16] = f2tf32(ar[it].z);
            dst[24] = f2tf32(ar[it].w);
        }
        #pragma unroll
        for (int j = 0; j < 2; j++) {
            int o  = (j * 512 + tid) * 4;
            int n  = o >> 5;
            int pk = o & 31;
            uint32_t* dst = &Bs[n * SPAD + pk];
            dst[0] = br[j].x; dst[1] = br[j].y;
            dst[2] = br[j].z; dst[3] = br[j].w;
        }
        __syncthreads();

        if (t < 7) {
            const float* Asrc = (t + 1 >= 4) ? A1 : A0;
            int kb = ((t + 1) & 3) * 32;
            #pragma unroll
            for (int it = 0; it < 2; it++) {
                int idx = tid + it * 512;
                int row = idx >> 3, tt = idx & 7;
                int grow = row0 + row;
                ar[it] = (grow < n_rows)
                    ? __ldg((const float4*)&Asrc[(size_t)grow * HIDDEN + kb + tt * 4])
                    : make_float4(0.f, 0.f, 0.f, 0.f);
            }
            const uint4* src = (const uint4*)&g_W1t[(t + 1) * 4096];
            #pragma unroll
            for (int j = 0; j < 2; j++) br[j] = __ldg(&src[j * 512 + tid]);
        }

        #pragma unroll
        for (int s = 0; s < 4; s++) {
            uint32_t a[2][4];
            #pragma unroll
            for (int mt = 0; mt < 2; mt++) {
                int r = Rw + mt * 16 + lg;
                int o0 = r * SPAD + q * 8 + 2 * s;
                int o1 = (r + 8) * SPAD + q * 8 + 2 * s;
                a[mt][0] = As[o0]; a[mt][2] = As[o0 + 1];
                a[mt][1] = As[o1]; a[mt][3] = As[o1 + 1];
            }
            uint32_t b[4][2];
            #pragma unroll
            for (int nt = 0; nt < 4; nt++) {
                int ob = (Nw + nt * 8 + lg) * SPAD + q * 8 + 2 * s;
                b[nt][0] = Bs[ob]; b[nt][1] = Bs[ob + 1];
            }
            #pragma unroll
            for (int mt = 0; mt < 2; mt++)
                #pragma unroll
                for (int nt = 0; nt < 4; nt++)
                    asm volatile(
                        "mma.sync.aligned.m16n8k8.row.col.f32.tf32.tf32.f32 "
                        "{%0,%1,%2,%3}, {%4,%5,%6,%7}, {%8,%9}, {%0,%1,%2,%3};"
                        : "+f"(c1[mt][nt][0]), "+f"(c1[mt][nt][1]),
                          "+f"(c1[mt][nt][2]), "+f"(c1[mt][nt][3])
                        : "r"(a[mt][0]), "r"(a[mt][1]),
                          "r"(a[mt][2]), "r"(a[mt][3]),
                          "r"(b[nt][0]), "r"(b[nt][1]));
        }
        __syncthreads();
    }

    // ---------------- phase 2: stage h, then x = h @ W2 + b2 -----------------
    #pragma unroll
    for (int mt = 0; mt < 2; mt++) {
        int r0 = Rw + mt * 16 + lg;
        int r1 = r0 + 8;
        #pragma unroll
        for (int nt = 0; nt < 4; nt++) {
            int col = Nw + nt * 8 + 2 * q;
            int lk0 = nt * 8 + 2 * q;
            float bb0 = sB1[col], bb1 = sB1[col + 1];
            float v0 = fmaxf(c1[mt][nt][0] + bb0, 0.f);
            float v1 = fmaxf(c1[mt][nt][1] + bb1, 0.f);
            float v2 = fmaxf(c1[mt][nt][2] + bb0, 0.f);
            float v3 = fmaxf(c1[mt][nt][3] + bb1, 0.f);
            int p0 = (lk0 & 3) * 8 + (lk0 >> 2);
            int p1 = ((lk0 + 1) & 3) * 8 + ((lk0 + 1) >> 2);
            uint32_t* hb = &Hs[wn * HS_W];
            hb[r0 * SPAD + p0] = f2tf32(v0);
            hb[r0 * SPAD + p1] = f2tf32(v1);
            hb[r1 * SPAD + p0] = f2tf32(v2);
            hb[r1 * SPAD + p1] = f2tf32(v3);
        }
    }

    float c2[2][4][4];
    #pragma unroll
    for (int i = 0; i < 2; i++)
        #pragma unroll
        for (int j = 0; j < 4; j++)
            #pragma unroll
            for (int t = 0; t < 4; t++) c2[i][j][t] = 0.0f;

    {
        const uint4* src = (const uint4*)g_W2t;
        #pragma unroll
        for (int j = 0; j < 2; j++) br[j] = __ldg(&src[j * 512 + tid]);
    }

    for (int s = 0; s < 4; s++) {
        #pragma unroll
        for (int j = 0; j < 2; j++) {
            int o  = (j * 512 + tid) * 4;
            int n  = o >> 5;
            int pk = o & 31;
            uint32_t* dst = &Bs2[n * SPAD + pk];
            dst[0] = br[j].x; dst[1] = br[j].y;
            dst[2] = br[j].z; dst[3] = br[j].w;
        }
        __syncthreads();

        if (s < 3) {
            const uint4* src = (const uint4*)&g_W2t[(s + 1) * 4096];
            #pragma unroll
            for (int j = 0; j < 2; j++) br[j] = __ldg(&src[j * 512 + tid]);
        }

        const uint32_t* Hb = &Hs[s * HS_W];
        #pragma unroll
        for (int ss = 0; ss < 4; ss++) {
            uint32_t a[2][4];
            #pragma unroll
            for (int mt = 0; mt < 2; mt++) {
                int r = Rw + mt * 16 + lg;
                int o0 = r * SPAD + q * 8 + 2 * ss;
                int o1 = (r + 8) * SPAD + q * 8 + 2 * ss;
                a[mt][0] = Hb[o0]; a[mt][2] = Hb[o0 + 1];
                a[mt][1] = Hb[o1]; a[mt][3] = Hb[o1 + 1];
            }
            uint32_t b[4][2];
            #pragma unroll
            for (int nt = 0; nt < 4; nt++) {
                int ob = (Nw + nt * 8 + lg) * SPAD + q * 8 + 2 * ss;
                b[nt][0] = Bs2[ob]; b[nt][1] = Bs2[ob + 1];
            }
            #pragma unroll
            for (int mt = 0; mt < 2; mt++)
                #pragma unroll
                for (int nt = 0; nt < 4; nt++)
                    asm volatile(
                        "mma.sync.aligned.m16n8k8.row.col.f32.tf32.tf32.f32 "
                        "{%0,%1,%2,%3}, {%4,%5,%6,%7}, {%8,%9}, {%0,%1,%2,%3};"
                        : "+f"(c2[mt][nt][0]), "+f"(c2[mt][nt][1]),
                          "+f"(c2[mt][nt][2]), "+f"(c2[mt][nt][3])
                        : "r"(a[mt][0]), "r"(a[mt][1]),
                          "r"(a[mt][2]), "r"(a[mt][3]),
                          "r"(b[nt][0]), "r"(b[nt][1]));
        }
        __syncthreads();
    }

    #pragma unroll
    for (int mt = 0; mt < 2; mt++) {
        int r0g = row0 + Rw + mt * 16 + lg;
        int r1g = r0g + 8;
        #pragma unroll
        for (int nt = 0; nt < 4; nt++) {
            int col = Nw + nt * 8 + 2 * q;
            float bb0 = sB2[col], bb1 = sB2[col + 1];
            if (r0g < n_rows)
                *(float2*)&out[(size_t)r0g * HIDDEN + col] =
                    make_float2(c2[mt][nt][0] + bb0, c2[mt][nt][1] + bb1);
            if (r1g < n_rows)
                *(float2*)&out[(size_t)r1g * HIDDEN + col] =
                    make_float2(c2[mt][nt][2] + bb0, c2[mt][nt][3] + bb1);
        }
    }
}

// ---------------- launcher ---------------------------------------------------
extern "C" void kernel_launch(void* const* d_in, const int* in_sizes, int n_in,
                              void* d_out, int out_size) {
    const float* node_attr  = (const float*)d_in[0];
    const void*  edge_index = d_in[1];
    const float* edge_attr  = (const float*)d_in[2];
    const float* W1         = (const float*)d_in[3];
    const float* b1         = (const float*)d_in[4];
    const float* W2         = (const float*)d_in[5];
    const float* b2         = (const float*)d_in[6];

    int n_nodes = in_sizes[0] / HIDDEN;
    int n_edges = in_sizes[1] / 2;

    size_t x_el  = (size_t)n_nodes * HIDDEN;
    size_t ei_el = 2 * (size_t)n_edges;
    size_t ea_el = (size_t)n_edges * HIDDEN;

    float* out   = (float*)d_out;
    float* out_x = out;

    size_t os = (size_t)out_size;
    bool idx64 = false;
    float*     out_ei_f   = nullptr;
    long long* out_ei_raw = nullptr;
    float*     out_ea     = nullptr;
    if (os == x_el + ei_el + ea_el) {
        idx64 = false;
        out_ei_f = out + x_el;
        out_ea   = out + x_el + ei_el;
    } else if (os == x_el + 2 * ei_el + ea_el) {
        idx64 = true;
        out_ei_raw = (long long*)(out + x_el);
        out_ea     = out + x_el + 2 * ei_el;
    }

    float* d_agg; cudaGetSymbolAddress((void**)&d_agg, g_agg);

    // 1. fused init: wconv (blocks 0-11) + zero agg (blocks 12+)
    init_kernel<<<2060, 256>>>(W1, W2, n_nodes);

    // 2. scatter + ea copy + ei copy + colsum
    {
        int blocks = 1184;
        int n_ei = 2 * n_edges;
        if (idx64) {
            const long long* eil = (const long long*)edge_index;
            scatter_copy_kernel<long long><<<blocks, 256>>>(
                (const float4*)edge_attr, eil + n_edges, (float4*)out_ea,
                eil, nullptr, out_ei_raw, n_ei, n_edges);
        } else {
            const int* eii = (const int*)edge_index;
            scatter_copy_kernel<int><<<blocks, 256>>>(
                (const float4*)edge_attr, eii + n_edges, (float4*)out_ea,
                eii, out_ei_f, nullptr, n_ei, n_edges);
        }
    }

    // 3. fold column means into bias
    b1eff_kernel<<<HIDDEN, HIDDEN>>>(W1, b1, n_nodes);

    // 4. fused MLP (512 threads, 16 warps)
    {
        int smem_bytes = ARENA_WORDS * 4;
        cudaFuncSetAttribute(fused_mlp_kernel,
                             cudaFuncAttributeMaxDynamicSharedMemorySize,
                             smem_bytes);
        int blocks = (n_nodes + 127) / 128;
        fused_mlp_kernel<<<blocks, 512, smem_bytes>>>(node_attr, d_agg, b2,
                                                      out_x, n_nodes);
    }
}